// round 1
// baseline (speedup 1.0000x reference)
#include <cuda_runtime.h>
#include <math.h>

#define N 4096
#define D 128
#define NBINS 2048
#define NT 256
#define BM 128
#define BK 32
#define LDP 132   // padded row stride for smem tiles (16B aligned, reduces store conflicts)

// Scratch (device globals are the sanctioned way to get scratch; no runtime allocs)
__device__ float  g_logits[(size_t)N * N];  // 64 MB
__device__ float  g_x2[N];
__device__ double g_rowsum[N];

// ---------------------------------------------------------------------------
// Kernel 0: x2[i] = ||f_i||^2
// ---------------------------------------------------------------------------
__global__ void x2_kernel(const float* __restrict__ F) {
    int i = blockIdx.x;
    float x = F[(size_t)i * D + threadIdx.x];
    float v = x * x;
    __shared__ float s[4];
    #pragma unroll
    for (int o = 16; o; o >>= 1) v += __shfl_down_sync(0xffffffffu, v, o);
    if ((threadIdx.x & 31) == 0) s[threadIdx.x >> 5] = v;
    __syncthreads();
    if (threadIdx.x == 0) g_x2[i] = s[0] + s[1] + s[2] + s[3];
}

// ---------------------------------------------------------------------------
// Kernel 1: Gram GEMM + logits epilogue.
// logits[i][j] = (i!=j && sq>0) ? -0.5*sqrt(x2_i + x2_j - 2*<f_i,f_j>) : 0
// (row-max subtraction is skipped: it cancels exactly in log_probs)
// ---------------------------------------------------------------------------
__global__ void __launch_bounds__(256) gram_kernel(const float* __restrict__ F) {
    __shared__ __align__(16) float As[BK][LDP];
    __shared__ __align__(16) float Bs[BK][LDP];
    int bi = blockIdx.y, bj = blockIdx.x;
    int t = threadIdx.x;
    int tx = t & 15, ty = t >> 4;
    int lr = t >> 3;          // row within 32-row load pass
    int lk = (t & 7) << 2;    // k offset (float4)
    const float* Ap = F + (size_t)bi * BM * D;
    const float* Bp = F + (size_t)bj * BM * D;

    float acc[8][8];
    #pragma unroll
    for (int r = 0; r < 8; r++)
        #pragma unroll
        for (int c = 0; c < 8; c++) acc[r][c] = 0.f;

    for (int kk = 0; kk < D; kk += BK) {
        #pragma unroll
        for (int p = 0; p < 4; p++) {
            int r = lr + p * 32;
            float4 a = *(const float4*)(Ap + (size_t)r * D + kk + lk);
            As[lk + 0][r] = a.x; As[lk + 1][r] = a.y;
            As[lk + 2][r] = a.z; As[lk + 3][r] = a.w;
            float4 b = *(const float4*)(Bp + (size_t)r * D + kk + lk);
            Bs[lk + 0][r] = b.x; Bs[lk + 1][r] = b.y;
            Bs[lk + 2][r] = b.z; Bs[lk + 3][r] = b.w;
        }
        __syncthreads();
        #pragma unroll
        for (int k = 0; k < BK; k++) {
            float4 a0 = *(const float4*)&As[k][ty * 8];
            float4 a1 = *(const float4*)&As[k][ty * 8 + 4];
            float4 b0 = *(const float4*)&Bs[k][tx * 8];
            float4 b1 = *(const float4*)&Bs[k][tx * 8 + 4];
            float a[8] = {a0.x, a0.y, a0.z, a0.w, a1.x, a1.y, a1.z, a1.w};
            float b[8] = {b0.x, b0.y, b0.z, b0.w, b1.x, b1.y, b1.z, b1.w};
            #pragma unroll
            for (int r = 0; r < 8; r++)
                #pragma unroll
                for (int c = 0; c < 8; c++)
                    acc[r][c] = fmaf(a[r], b[c], acc[r][c]);
        }
        __syncthreads();
    }

    #pragma unroll
    for (int r = 0; r < 8; r++) {
        int gi = bi * BM + ty * 8 + r;
        float x2i = g_x2[gi];
        float o[8];
        #pragma unroll
        for (int c = 0; c < 8; c++) {
            int gj = bj * BM + tx * 8 + c;
            float sq = x2i + g_x2[gj] - 2.f * acc[r][c];
            o[c] = (gi != gj && sq > 0.f) ? (-0.5f * sqrtf(sq)) : 0.f;
        }
        float4* dst = (float4*)(g_logits + (size_t)gi * N + bj * BM + tx * 8);
        dst[0] = make_float4(o[0], o[1], o[2], o[3]);
        dst[1] = make_float4(o[4], o[5], o[6], o[7]);
    }
}

// ---------------------------------------------------------------------------
// Block scans (256 threads)
// ---------------------------------------------------------------------------
__device__ __forceinline__ int exscan_int(int v, int t, int* total) {
    __shared__ int ws[8];
    __syncthreads();
    int lane = t & 31, w = t >> 5;
    int x = v;
    #pragma unroll
    for (int o = 1; o < 32; o <<= 1) {
        int y = __shfl_up_sync(0xffffffffu, x, o);
        if (lane >= o) x += y;
    }
    if (lane == 31) ws[w] = x;
    __syncthreads();
    if (w == 0) {
        int s = (lane < 8) ? ws[lane] : 0;
        #pragma unroll
        for (int o = 1; o < 32; o <<= 1) {
            int y = __shfl_up_sync(0xffffffffu, s, o);
            if (lane >= o) s += y;
        }
        if (lane < 8) ws[lane] = s;
    }
    __syncthreads();
    *total = ws[7];
    int off = (w == 0) ? 0 : ws[w - 1];
    return off + x - v;
}

__device__ __forceinline__ float exscan_float(float v, int t, float* total) {
    __shared__ float wsf[8];
    __syncthreads();
    int lane = t & 31, w = t >> 5;
    float x = v;
    #pragma unroll
    for (int o = 1; o < 32; o <<= 1) {
        float y = __shfl_up_sync(0xffffffffu, x, o);
        if (lane >= o) x += y;
    }
    if (lane == 31) wsf[w] = x;
    __syncthreads();
    if (w == 0) {
        float s = (lane < 8) ? wsf[lane] : 0.f;
        #pragma unroll
        for (int o = 1; o < 32; o <<= 1) {
            float y = __shfl_up_sync(0xffffffffu, s, o);
            if (lane >= o) s += y;
        }
        if (lane < 8) wsf[lane] = s;
    }
    __syncthreads();
    *total = wsf[7];
    float off = (w == 0) ? 0.f : wsf[w - 1];
    return off + x - v;
}

// ---------------------------------------------------------------------------
// Kernel 2: one CTA per row. Counting-sort into NBINS buckets, bin suffix
// sums, then S(k) = sufsum[bin+1] + within-bin exact compare. Accumulates
//   rowsum = sum_k logits[k] - 0.5*(sum_k log S_th(k) + sum_k log S_sh(k))
// ---------------------------------------------------------------------------
__global__ void __launch_bounds__(NT) row_kernel(const float* __restrict__ theta,
                                                 const float* __restrict__ shift) {
    extern __shared__ __align__(16) unsigned char sm[];
    float* ex     = (float*)sm;                       // N
    float* th     = ex + N;                           // N
    float* sufsum = th + N;                           // NBINS+1
    int*   start  = (int*)(sufsum + NBINS + 1);       // NBINS+1
    int*   cnt    = start + NBINS + 1;                // NBINS
    unsigned short* sidx = (unsigned short*)(cnt + NBINS); // N
    __shared__ double red[NT];

    const int i = blockIdx.x;
    const int t = threadIdx.x;
    const int PER = NBINS / NT; // 8

    // exp(logits) row; diagonal excluded from sums (ex=0) and from sum of logits
    float sumLg = 0.f;
    for (int j = t; j < N; j += NT) {
        float v = g_logits[(size_t)i * N + j];
        float e = __expf(v);
        if (j == i) e = 0.f; else sumLg += v;
        ex[j] = e;
    }

    double accLogs = 0.0;

    #pragma unroll 1
    for (int mat = 0; mat < 2; mat++) {
        const float* M = mat ? shift : theta;
        const float scale = mat ? (NBINS / 100.0f) : (NBINS / 180.0f);

        __syncthreads();
        for (int b = t; b < NBINS; b += NT) { cnt[b] = 0; sufsum[b] = 0.f; }
        if (t == 0) sufsum[NBINS] = 0.f;
        for (int j = t; j < N; j += NT) th[j] = M[(size_t)i * N + j];
        __syncthreads();

        // count + per-bin exp sums (diagonal contributes 0)
        for (int j = t; j < N; j += NT) {
            int b = (int)(th[j] * scale);
            b = b < 0 ? 0 : (b > NBINS - 1 ? NBINS - 1 : b);
            atomicAdd(&cnt[b], 1);
            atomicAdd(&sufsum[b], ex[j]);
        }
        __syncthreads();

        // suffix-sum over bins (in place, 8 bins/thread + chunk scan)
        {
            int base = t * PER;
            float loc[PER];
            float tot = 0.f;
            #pragma unroll
            for (int q = PER - 1; q >= 0; q--) { tot += sufsum[base + q]; loc[q] = tot; }
            float total;
            float excl = exscan_float(tot, t, &total);
            float off = total - excl - tot; // sum of higher chunks
            #pragma unroll
            for (int q = 0; q < PER; q++) sufsum[base + q] = loc[q] + off;
        }
        // exclusive prefix of counts -> start[]; cursor copy in cnt[]
        {
            int base = t * PER;
            int loc[PER];
            int s = 0;
            #pragma unroll
            for (int q = 0; q < PER; q++) { loc[q] = s; s += cnt[base + q]; }
            int total;
            int excl = exscan_int(s, t, &total);
            #pragma unroll
            for (int q = 0; q < PER; q++) {
                int v = excl + loc[q];
                start[base + q] = v;
                cnt[base + q] = v;
            }
            if (t == 0) start[NBINS] = total;
        }
        __syncthreads();

        // scatter indices by bin
        for (int j = t; j < N; j += NT) {
            int b = (int)(th[j] * scale);
            b = b < 0 ? 0 : (b > NBINS - 1 ? NBINS - 1 : b);
            int pos = atomicAdd(&cnt[b], 1);
            sidx[pos] = (unsigned short)j;
        }
        __syncthreads();

        // per-k masked sum: higher bins via suffix, same bin via exact compare
        float accF = 0.f;
        for (int k = t; k < N; k += NT) {
            if (k == i) continue;
            float v = th[k];
            int b = (int)(v * scale);
            b = b < 0 ? 0 : (b > NBINS - 1 ? NBINS - 1 : b);
            float S = sufsum[b + 1];
            int e1 = start[b + 1];
            for (int q = start[b]; q < e1; q++) {
                int jj = sidx[q];
                if (th[jj] >= v) S += ex[jj];
            }
            accF += __logf(S);
        }
        accLogs += (double)accF;
    }

    __syncthreads();
    red[t] = (double)sumLg - 0.5 * accLogs;
    __syncthreads();
    #pragma unroll
    for (int o = NT / 2; o; o >>= 1) {
        if (t < o) red[t] += red[t + o];
        __syncthreads();
    }
    if (t == 0) g_rowsum[i] = red[0];
}

// ---------------------------------------------------------------------------
// Kernel 3: deterministic final reduce (double)
// ---------------------------------------------------------------------------
__global__ void reduce_kernel(float* __restrict__ out) {
    __shared__ double sh[NT];
    double s = 0.0;
    for (int i = threadIdx.x; i < N; i += NT) s += g_rowsum[i];
    sh[threadIdx.x] = s;
    __syncthreads();
    for (int o = NT / 2; o; o >>= 1) {
        if (threadIdx.x < o) sh[threadIdx.x] += sh[threadIdx.x + o];
        __syncthreads();
    }
    if (threadIdx.x == 0)
        out[0] = (float)(-sh[0] / ((double)N * (double)(N - 1)));
}

// ---------------------------------------------------------------------------
extern "C" void kernel_launch(void* const* d_in, const int* in_sizes, int n_in,
                              void* d_out, int out_size) {
    const float* theta = (const float*)d_in[0];
    const float* shift = (const float*)d_in[1];
    const float* feats = (const float*)d_in[2];
    float* out = (float*)d_out;

    x2_kernel<<<N, 128>>>(feats);

    dim3 grid(N / BM, N / BM);
    gram_kernel<<<grid, 256>>>(feats);

    size_t smem = (size_t)N * 4     // ex
                + (size_t)N * 4     // th
                + (NBINS + 1) * 4   // sufsum
                + (NBINS + 1) * 4   // start
                + (size_t)NBINS * 4 // cnt
                + (size_t)N * 2;    // sidx
    cudaFuncSetAttribute(row_kernel, cudaFuncAttributeMaxDynamicSharedMemorySize, (int)smem);
    row_kernel<<<N, NT, smem>>>(theta, shift);

    reduce_kernel<<<1, NT>>>(out);
}

// round 2
// speedup vs baseline: 1.5736x; 1.5736x over previous
#include <cuda_runtime.h>
#include <math.h>

#define N 4096
#define D 128
#define NBINS 2048
#define NT 256
#define BM 128
#define BK 32
#define LDP 132

__device__ float  g_logits[(size_t)N * N];  // 64 MB scratch: logits = -dist/2
__device__ float  g_x2[N];
__device__ double g_rowsum[N];

// ---------------------------------------------------------------------------
// fast math on FMA/ALU pipes (MUFU avoidance)
// ---------------------------------------------------------------------------
__device__ __forceinline__ float fast_sqrt(float x) {
    // rsqrt bit-hack + 3 Newton iterations, then sqrt = x * rsqrt(x). ~1e-7 rel.
    float xh = 0.5f * x;
    float y = __int_as_float(0x5f375a86 - (__float_as_int(x) >> 1));
    y = y * fmaf(-xh * y, y, 1.5f);
    y = y * fmaf(-xh * y, y, 1.5f);
    y = y * fmaf(-xh * y, y, 1.5f);
    return x * y;
}

__device__ __forceinline__ float fast_exp(float x) {
    // x in [-20, 0]; exp(x) = 2^(x*log2e); deg-6 Taylor on f in [-0.5, 0.5]. ~1e-7 rel.
    float t = x * 1.4426950408889634f;
    float n = rintf(t);
    float f = t - n;
    float p = fmaf(f, 1.5403530e-4f, 0.0013333558f);
    p = fmaf(f, p, 0.0096181291f);
    p = fmaf(f, p, 0.0555041087f);
    p = fmaf(f, p, 0.2402265069f);
    p = fmaf(f, p, 0.6931471806f);
    p = fmaf(f, p, 1.0f);
    int ei = (int)n;
    return __int_as_float((ei + 127) << 23) * p;
}

// ---------------------------------------------------------------------------
// Kernel 0: x2[i] = ||f_i||^2
// ---------------------------------------------------------------------------
__global__ void x2_kernel(const float* __restrict__ F) {
    int i = blockIdx.x;
    float x = F[(size_t)i * D + threadIdx.x];
    float v = x * x;
    __shared__ float s[4];
    #pragma unroll
    for (int o = 16; o; o >>= 1) v += __shfl_down_sync(0xffffffffu, v, o);
    if ((threadIdx.x & 31) == 0) s[threadIdx.x >> 5] = v;
    __syncthreads();
    if (threadIdx.x == 0) g_x2[i] = s[0] + s[1] + s[2] + s[3];
}

// ---------------------------------------------------------------------------
// Kernel 1: symmetric Gram GEMM + logits epilogue (bi <= bj only, mirrored)
// ---------------------------------------------------------------------------
__global__ void __launch_bounds__(256, 2) gram_kernel(const float* __restrict__ F) {
    int bi = blockIdx.y, bj = blockIdx.x;
    if (bj < bi) return;  // symmetry: compute upper-triangular tiles only

    __shared__ __align__(16) float As[BK][LDP];
    __shared__ __align__(16) float Bs[BK][LDP];
    int t = threadIdx.x;
    int tx = t & 15, ty = t >> 4;
    int lr = t >> 3;
    int lk = (t & 7) << 2;
    const float* Ap = F + (size_t)bi * BM * D;
    const float* Bp = F + (size_t)bj * BM * D;

    float acc[8][8];
    #pragma unroll
    for (int r = 0; r < 8; r++)
        #pragma unroll
        for (int c = 0; c < 8; c++) acc[r][c] = 0.f;

    for (int kk = 0; kk < D; kk += BK) {
        #pragma unroll
        for (int p = 0; p < 4; p++) {
            int r = lr + p * 32;
            float4 a = *(const float4*)(Ap + (size_t)r * D + kk + lk);
            As[lk + 0][r] = a.x; As[lk + 1][r] = a.y;
            As[lk + 2][r] = a.z; As[lk + 3][r] = a.w;
            float4 b = *(const float4*)(Bp + (size_t)r * D + kk + lk);
            Bs[lk + 0][r] = b.x; Bs[lk + 1][r] = b.y;
            Bs[lk + 2][r] = b.z; Bs[lk + 3][r] = b.w;
        }
        __syncthreads();
        #pragma unroll
        for (int k = 0; k < BK; k++) {
            float4 a0 = *(const float4*)&As[k][ty * 8];
            float4 a1 = *(const float4*)&As[k][ty * 8 + 4];
            float4 b0 = *(const float4*)&Bs[k][tx * 8];
            float4 b1 = *(const float4*)&Bs[k][tx * 8 + 4];
            float a[8] = {a0.x, a0.y, a0.z, a0.w, a1.x, a1.y, a1.z, a1.w};
            float b[8] = {b0.x, b0.y, b0.z, b0.w, b1.x, b1.y, b1.z, b1.w};
            #pragma unroll
            for (int r = 0; r < 8; r++)
                #pragma unroll
                for (int c = 0; c < 8; c++)
                    acc[r][c] = fmaf(a[r], b[c], acc[r][c]);
        }
        __syncthreads();
    }

    // epilogue: acc -> logits (in place), fast_sqrt on FMA pipe
    #pragma unroll
    for (int r = 0; r < 8; r++) {
        int gi = bi * BM + ty * 8 + r;
        float x2i = g_x2[gi];
        #pragma unroll
        for (int c = 0; c < 8; c++) {
            int gj = bj * BM + tx * 8 + c;
            float sq = x2i + g_x2[gj] - 2.f * acc[r][c];
            acc[r][c] = (gi != gj && sq > 0.f) ? (-0.5f * fast_sqrt(sq)) : 0.f;
        }
    }
    // normal store (rows gi, cols gj)
    #pragma unroll
    for (int r = 0; r < 8; r++) {
        int gi = bi * BM + ty * 8 + r;
        float4* dst = (float4*)(g_logits + (size_t)gi * N + bj * BM + tx * 8);
        dst[0] = make_float4(acc[r][0], acc[r][1], acc[r][2], acc[r][3]);
        dst[1] = make_float4(acc[r][4], acc[r][5], acc[r][6], acc[r][7]);
    }
    // mirror store into (bj, bi) tile
    if (bi != bj) {
        #pragma unroll
        for (int c = 0; c < 8; c++) {
            int gjm = bj * BM + tx * 8 + c;          // mirrored row
            int gim = bi * BM + ty * 8;              // mirrored col base
            float4* dst = (float4*)(g_logits + (size_t)gjm * N + gim);
            dst[0] = make_float4(acc[0][c], acc[1][c], acc[2][c], acc[3][c]);
            dst[1] = make_float4(acc[4][c], acc[5][c], acc[6][c], acc[7][c]);
        }
    }
}

// ---------------------------------------------------------------------------
// Block scans (256 threads)
// ---------------------------------------------------------------------------
__device__ __forceinline__ int exscan_int(int v, int t, int* total) {
    __shared__ int ws[8];
    __syncthreads();
    int lane = t & 31, w = t >> 5;
    int x = v;
    #pragma unroll
    for (int o = 1; o < 32; o <<= 1) {
        int y = __shfl_up_sync(0xffffffffu, x, o);
        if (lane >= o) x += y;
    }
    if (lane == 31) ws[w] = x;
    __syncthreads();
    if (w == 0) {
        int s = (lane < 8) ? ws[lane] : 0;
        #pragma unroll
        for (int o = 1; o < 32; o <<= 1) {
            int y = __shfl_up_sync(0xffffffffu, s, o);
            if (lane >= o) s += y;
        }
        if (lane < 8) ws[lane] = s;
    }
    __syncthreads();
    *total = ws[7];
    int off = (w == 0) ? 0 : ws[w - 1];
    return off + x - v;
}

__device__ __forceinline__ float exscan_float(float v, int t, float* total) {
    __shared__ float wsf[8];
    __syncthreads();
    int lane = t & 31, w = t >> 5;
    float x = v;
    #pragma unroll
    for (int o = 1; o < 32; o <<= 1) {
        float y = __shfl_up_sync(0xffffffffu, x, o);
        if (lane >= o) x += y;
    }
    if (lane == 31) wsf[w] = x;
    __syncthreads();
    if (w == 0) {
        float s = (lane < 8) ? wsf[lane] : 0.f;
        #pragma unroll
        for (int o = 1; o < 32; o <<= 1) {
            float y = __shfl_up_sync(0xffffffffu, s, o);
            if (lane >= o) s += y;
        }
        if (lane < 8) wsf[lane] = s;
    }
    __syncthreads();
    *total = wsf[7];
    float off = (w == 0) ? 0.f : wsf[w - 1];
    return off + x - v;
}

// ---------------------------------------------------------------------------
// Kernel 2: one CTA per row. Counting-sort into bins + suffix sums; per-k:
// S(k) = sufsum[bin+1] + exact within-bin scan. Sum of log S via running
// mantissa product + exponent stripping (no per-k logf).
// ---------------------------------------------------------------------------
__global__ void __launch_bounds__(NT, 3) row_kernel(const float* __restrict__ theta,
                                                    const float* __restrict__ shift) {
    extern __shared__ __align__(16) unsigned char sm[];
    float* sval   = (float*)sm;                       // N (sorted values)
    float* sex    = sval + N;                         // N (sorted exp-logits)
    float* sufsum = sex + N;                          // NBINS+1
    int*   start  = (int*)(sufsum + NBINS + 1);       // NBINS+1
    int*   cnt    = start + NBINS + 1;                // NBINS
    __shared__ double red[NT];

    const int i = blockIdx.x;
    const int t = threadIdx.x;
    const int PER = NBINS / NT;  // 8
    const int JPT = N / NT;      // 16

    // exp(logits) for own elements (registers); diagonal marked ex=0.
    float vex[JPT];
    float sumLg = 0.f;
    #pragma unroll
    for (int q = 0; q < JPT; q++) {
        int j = t + q * NT;
        float v = g_logits[(size_t)i * N + j];
        sumLg += v;  // diagonal stored as 0, contributes nothing
        vex[q] = (j == i) ? 0.f : fast_exp(v);
    }

    float prod = 1.f;
    int eacc = 0, cntk = 0;

    #pragma unroll 1
    for (int mat = 0; mat < 2; mat++) {
        const float* M = mat ? shift : theta;
        const float scale = mat ? (NBINS / 100.0f) : (NBINS / 180.0f);

        float vth[JPT];
        #pragma unroll
        for (int q = 0; q < JPT; q++) vth[q] = M[(size_t)i * N + t + q * NT];

        __syncthreads();  // previous per-k phase done with sufsum/start/sval/sex
        for (int b = t; b < NBINS; b += NT) { cnt[b] = 0; sufsum[b] = 0.f; }
        if (t == 0) sufsum[NBINS] = 0.f;
        __syncthreads();

        // count + per-bin exp sums (diagonal ex=0 contributes nothing)
        #pragma unroll
        for (int q = 0; q < JPT; q++) {
            int b = (int)(vth[q] * scale);
            b = b < 0 ? 0 : (b > NBINS - 1 ? NBINS - 1 : b);
            atomicAdd(&cnt[b], 1);
            atomicAdd(&sufsum[b], vex[q]);
        }
        __syncthreads();

        // suffix-sum over bins
        {
            int base = t * PER;
            float loc[PER];
            float tot = 0.f;
            #pragma unroll
            for (int q = PER - 1; q >= 0; q--) { tot += sufsum[base + q]; loc[q] = tot; }
            float total;
            float excl = exscan_float(tot, t, &total);
            float off = total - excl - tot;  // sum of higher chunks
            #pragma unroll
            for (int q = 0; q < PER; q++) sufsum[base + q] = loc[q] + off;
        }
        // exclusive prefix of counts -> start[]; cursor copy in cnt[]
        {
            int base = t * PER;
            int loc[PER];
            int s = 0;
            #pragma unroll
            for (int q = 0; q < PER; q++) { loc[q] = s; s += cnt[base + q]; }
            int total;
            int excl = exscan_int(s, t, &total);
            #pragma unroll
            for (int q = 0; q < PER; q++) {
                int v = excl + loc[q];
                start[base + q] = v;
                cnt[base + q] = v;
            }
            if (t == 0) start[NBINS] = total;
        }
        __syncthreads();

        // scatter values + exps by bin
        #pragma unroll
        for (int q = 0; q < JPT; q++) {
            int b = (int)(vth[q] * scale);
            b = b < 0 ? 0 : (b > NBINS - 1 ? NBINS - 1 : b);
            int pos = atomicAdd(&cnt[b], 1);
            sval[pos] = vth[q];
            sex[pos]  = vex[q];
        }
        __syncthreads();

        // per-k: skip diagonal (sex==0); higher bins via suffix, same bin exact
        for (int k = t; k < N; k += NT) {
            float e0 = sex[k];
            if (e0 == 0.f) continue;  // diagonal marker
            float v = sval[k];
            int b = (int)(v * scale);
            b = b < 0 ? 0 : (b > NBINS - 1 ? NBINS - 1 : b);
            float S = sufsum[b + 1];
            int q1 = start[b + 1];
            for (int q = start[b]; q < q1; q++) {
                if (sval[q] >= v) S += sex[q];
            }
            // running product with exponent stripping: sum(log S) deferred
            prod *= S;
            unsigned pb = __float_as_uint(prod);
            eacc += (int)(pb >> 23);
            prod = __uint_as_float((pb & 0x007fffffu) | 0x3f800000u);
            cntk++;
        }
    }

    double logsum = ((double)(eacc - 127 * cntk)) * 0.6931471805599453
                  + (double)__logf(prod);
    red[t] = (double)sumLg - 0.5 * logsum;
    __syncthreads();
    #pragma unroll
    for (int o = NT / 2; o; o >>= 1) {
        if (t < o) red[t] += red[t + o];
        __syncthreads();
    }
    if (t == 0) g_rowsum[i] = red[0];
}

// ---------------------------------------------------------------------------
// Kernel 3: deterministic final reduce (double)
// ---------------------------------------------------------------------------
__global__ void reduce_kernel(float* __restrict__ out) {
    __shared__ double sh[NT];
    double s = 0.0;
    for (int i = threadIdx.x; i < N; i += NT) s += g_rowsum[i];
    sh[threadIdx.x] = s;
    __syncthreads();
    for (int o = NT / 2; o; o >>= 1) {
        if (threadIdx.x < o) sh[threadIdx.x] += sh[threadIdx.x + o];
        __syncthreads();
    }
    if (threadIdx.x == 0)
        out[0] = (float)(-sh[0] / ((double)N * (double)(N - 1)));
}

// ---------------------------------------------------------------------------
extern "C" void kernel_launch(void* const* d_in, const int* in_sizes, int n_in,
                              void* d_out, int out_size) {
    const float* theta = (const float*)d_in[0];
    const float* shift = (const float*)d_in[1];
    const float* feats = (const float*)d_in[2];
    float* out = (float*)d_out;

    x2_kernel<<<N, 128>>>(feats);

    dim3 grid(N / BM, N / BM);
    gram_kernel<<<grid, 256>>>(feats);

    size_t smem = (size_t)N * 4          // sval
                + (size_t)N * 4          // sex
                + (NBINS + 1) * 4        // sufsum
                + (NBINS + 1) * 4        // start
                + (size_t)NBINS * 4;     // cnt
    cudaFuncSetAttribute(row_kernel, cudaFuncAttributeMaxDynamicSharedMemorySize, (int)smem);
    row_kernel<<<N, NT, smem>>>(theta, shift);

    reduce_kernel<<<1, NT>>>(out);
}

// round 5
// speedup vs baseline: 1.6476x; 1.0470x over previous
#include <cuda_runtime.h>
#include <math.h>
#include <cstdint>

#define N 4096
#define D 128
#define NBINS 2048
#define NT 256
#define BM 128
#define BK 32
#define LDP 132

__device__ float  g_logits[(size_t)N * N];  // 64 MB scratch: logits = -dist/2
__device__ float  g_x2[N];
__device__ double g_rowsum[N];
__device__ int    g_done;

// ---------------------------------------------------------------------------
// fast math on FMA/ALU pipes (MUFU avoidance)
// ---------------------------------------------------------------------------
__device__ __forceinline__ float fast_sqrt(float x) {
    float xh = 0.5f * x;
    float y = __int_as_float(0x5f375a86 - (__float_as_int(x) >> 1));
    y = y * fmaf(-xh * y, y, 1.5f);
    y = y * fmaf(-xh * y, y, 1.5f);
    y = y * fmaf(-xh * y, y, 1.5f);
    return x * y;
}
__device__ __forceinline__ float fast_exp(float x) {
    float t = x * 1.4426950408889634f;
    float n = rintf(t);
    float f = t - n;
    float p = fmaf(f, 1.5403530e-4f, 0.0013333558f);
    p = fmaf(f, p, 0.0096181291f);
    p = fmaf(f, p, 0.0555041087f);
    p = fmaf(f, p, 0.2402265069f);
    p = fmaf(f, p, 0.6931471806f);
    p = fmaf(f, p, 1.0f);
    return __int_as_float(((int)n + 127) << 23) * p;
}

// ---------------------------------------------------------------------------
// Kernel 0: x2[i] = ||f_i||^2 (+ reset completion counter)
// ---------------------------------------------------------------------------
__global__ void x2_kernel(const float* __restrict__ F) {
    int i = blockIdx.x;
    if (i == 0 && threadIdx.x == 0) g_done = 0;
    float x = F[(size_t)i * D + threadIdx.x];
    float v = x * x;
    __shared__ float s[4];
    #pragma unroll
    for (int o = 16; o; o >>= 1) v += __shfl_down_sync(0xffffffffu, v, o);
    if ((threadIdx.x & 31) == 0) s[threadIdx.x >> 5] = v;
    __syncthreads();
    if (threadIdx.x == 0) g_x2[i] = s[0] + s[1] + s[2] + s[3];
}

// ---------------------------------------------------------------------------
// Kernel 1: symmetric Gram GEMM + logits epilogue (bi <= bj only, mirrored)
// ---------------------------------------------------------------------------
__global__ void __launch_bounds__(256, 2) gram_kernel(const float* __restrict__ F) {
    int bi = blockIdx.y, bj = blockIdx.x;
    if (bj < bi) return;

    __shared__ __align__(16) float As[BK][LDP];
    __shared__ __align__(16) float Bs[BK][LDP];
    int t = threadIdx.x;
    int tx = t & 15, ty = t >> 4;
    int lr = t >> 3;
    int lk = (t & 7) << 2;
    const float* Ap = F + (size_t)bi * BM * D;
    const float* Bp = F + (size_t)bj * BM * D;

    float acc[8][8];
    #pragma unroll
    for (int r = 0; r < 8; r++)
        #pragma unroll
        for (int c = 0; c < 8; c++) acc[r][c] = 0.f;

    for (int kk = 0; kk < D; kk += BK) {
        #pragma unroll
        for (int p = 0; p < 4; p++) {
            int r = lr + p * 32;
            float4 a = *(const float4*)(Ap + (size_t)r * D + kk + lk);
            As[lk + 0][r] = a.x; As[lk + 1][r] = a.y;
            As[lk + 2][r] = a.z; As[lk + 3][r] = a.w;
            float4 b = *(const float4*)(Bp + (size_t)r * D + kk + lk);
            Bs[lk + 0][r] = b.x; Bs[lk + 1][r] = b.y;
            Bs[lk + 2][r] = b.z; Bs[lk + 3][r] = b.w;
        }
        __syncthreads();
        #pragma unroll
        for (int k = 0; k < BK; k++) {
            float4 a0 = *(const float4*)&As[k][ty * 8];
            float4 a1 = *(const float4*)&As[k][ty * 8 + 4];
            float4 b0 = *(const float4*)&Bs[k][tx * 8];
            float4 b1 = *(const float4*)&Bs[k][tx * 8 + 4];
            float a[8] = {a0.x, a0.y, a0.z, a0.w, a1.x, a1.y, a1.z, a1.w};
            float b[8] = {b0.x, b0.y, b0.z, b0.w, b1.x, b1.y, b1.z, b1.w};
            #pragma unroll
            for (int r = 0; r < 8; r++)
                #pragma unroll
                for (int c = 0; c < 8; c++)
                    acc[r][c] = fmaf(a[r], b[c], acc[r][c]);
        }
        __syncthreads();
    }

    #pragma unroll
    for (int r = 0; r < 8; r++) {
        int gi = bi * BM + ty * 8 + r;
        float x2i = g_x2[gi];
        #pragma unroll
        for (int c = 0; c < 8; c++) {
            int gj = bj * BM + tx * 8 + c;
            float sq = x2i + g_x2[gj] - 2.f * acc[r][c];
            acc[r][c] = (gi != gj && sq > 0.f) ? (-0.5f * fast_sqrt(sq)) : 0.f;
        }
    }
    #pragma unroll
    for (int r = 0; r < 8; r++) {
        int gi = bi * BM + ty * 8 + r;
        float4* dst = (float4*)(g_logits + (size_t)gi * N + bj * BM + tx * 8);
        dst[0] = make_float4(acc[r][0], acc[r][1], acc[r][2], acc[r][3]);
        dst[1] = make_float4(acc[r][4], acc[r][5], acc[r][6], acc[r][7]);
    }
    if (bi != bj) {
        #pragma unroll
        for (int c = 0; c < 8; c++) {
            int gjm = bj * BM + tx * 8 + c;
            int gim = bi * BM + ty * 8;
            float4* dst = (float4*)(g_logits + (size_t)gjm * N + gim);
            dst[0] = make_float4(acc[0][c], acc[1][c], acc[2][c], acc[3][c]);
            dst[1] = make_float4(acc[4][c], acc[5][c], acc[6][c], acc[7][c]);
        }
    }
}

// ---------------------------------------------------------------------------
// Block scans (256 threads)
// ---------------------------------------------------------------------------
__device__ __forceinline__ int exscan_int(int v, int t, int* total) {
    __shared__ int ws[8];
    __syncthreads();
    int lane = t & 31, w = t >> 5;
    int x = v;
    #pragma unroll
    for (int o = 1; o < 32; o <<= 1) {
        int y = __shfl_up_sync(0xffffffffu, x, o);
        if (lane >= o) x += y;
    }
    if (lane == 31) ws[w] = x;
    __syncthreads();
    if (w == 0) {
        int s = (lane < 8) ? ws[lane] : 0;
        #pragma unroll
        for (int o = 1; o < 32; o <<= 1) {
            int y = __shfl_up_sync(0xffffffffu, s, o);
            if (lane >= o) s += y;
        }
        if (lane < 8) ws[lane] = s;
    }
    __syncthreads();
    *total = ws[7];
    int off = (w == 0) ? 0 : ws[w - 1];
    return off + x - v;
}

__device__ __forceinline__ float exscan_float(float v, int t, float* total) {
    __shared__ float wsf[8];
    __syncthreads();
    int lane = t & 31, w = t >> 5;
    float x = v;
    #pragma unroll
    for (int o = 1; o < 32; o <<= 1) {
        float y = __shfl_up_sync(0xffffffffu, x, o);
        if (lane >= o) x += y;
    }
    if (lane == 31) wsf[w] = x;
    __syncthreads();
    if (w == 0) {
        float s = (lane < 8) ? wsf[lane] : 0.f;
        #pragma unroll
        for (int o = 1; o < 32; o <<= 1) {
            float y = __shfl_up_sync(0xffffffffu, s, o);
            if (lane >= o) s += y;
        }
        if (lane < 8) wsf[lane] = s;
    }
    __syncthreads();
    *total = wsf[7];
    float off = (w == 0) ? 0.f : wsf[w - 1];
    return off + x - v;
}

// ---------------------------------------------------------------------------
// Kernel 2: per-row counting-sort + suffix sums + masked log-sums.
// sorted (val, ex) packed as float2 -> one LDS.64 per element in hot loop.
// Last CTA (atomic counter) does the deterministic final reduce.
// ---------------------------------------------------------------------------
__global__ void __launch_bounds__(NT, 3) row_kernel(const float* __restrict__ theta,
                                                    const float* __restrict__ shift,
                                                    float* __restrict__ out) {
    extern __shared__ __align__(16) unsigned char sm[];
    float2* spair  = (float2*)sm;                     // N  (sorted {val, ex})
    float*  sufsum = (float*)(spair + N);             // NBINS+1
    int*    start  = (int*)(sufsum + NBINS + 1);      // NBINS+1
    int*    cnt    = start + NBINS + 1;               // NBINS
    __shared__ double red[NT];
    __shared__ int lastFlag;

    const int i = blockIdx.x;
    const int t = threadIdx.x;
    const int PER = NBINS / NT;  // 8
    const int JPT = N / NT;      // 16

    float vex[JPT];
    float sumLg = 0.f;
    #pragma unroll
    for (int q = 0; q < JPT; q++) {
        int j = t + q * NT;
        float v = g_logits[(size_t)i * N + j];
        sumLg += v;  // diagonal stored as 0
        vex[q] = (j == i) ? 0.f : fast_exp(v);
    }

    float prod = 1.f;
    int eacc = 0, cntk = 0;

    #pragma unroll 1
    for (int mat = 0; mat < 2; mat++) {
        const float* M = mat ? shift : theta;
        const float scale = mat ? (NBINS / 100.0f) : (NBINS / 180.0f);

        float vth[JPT];
        #pragma unroll
        for (int q = 0; q < JPT; q++) vth[q] = M[(size_t)i * N + t + q * NT];

        __syncthreads();
        for (int b = t; b < NBINS; b += NT) { cnt[b] = 0; sufsum[b] = 0.f; }
        if (t == 0) sufsum[NBINS] = 0.f;
        __syncthreads();

        #pragma unroll
        for (int q = 0; q < JPT; q++) {
            int b = (int)(vth[q] * scale);
            b = b < 0 ? 0 : (b > NBINS - 1 ? NBINS - 1 : b);
            atomicAdd(&cnt[b], 1);
            atomicAdd(&sufsum[b], vex[q]);
        }
        __syncthreads();

        {   // suffix-sum over bins
            int base = t * PER;
            float loc[PER];
            float tot = 0.f;
            #pragma unroll
            for (int q = PER - 1; q >= 0; q--) { tot += sufsum[base + q]; loc[q] = tot; }
            float total;
            float excl = exscan_float(tot, t, &total);
            float off = total - excl - tot;
            #pragma unroll
            for (int q = 0; q < PER; q++) sufsum[base + q] = loc[q] + off;
        }
        {   // exclusive prefix of counts
            int base = t * PER;
            int loc[PER];
            int s = 0;
            #pragma unroll
            for (int q = 0; q < PER; q++) { loc[q] = s; s += cnt[base + q]; }
            int total;
            int excl = exscan_int(s, t, &total);
            #pragma unroll
            for (int q = 0; q < PER; q++) {
                int v = excl + loc[q];
                start[base + q] = v;
                cnt[base + q] = v;
            }
            if (t == 0) start[NBINS] = total;
        }
        __syncthreads();

        #pragma unroll
        for (int q = 0; q < JPT; q++) {
            int b = (int)(vth[q] * scale);
            b = b < 0 ? 0 : (b > NBINS - 1 ? NBINS - 1 : b);
            int pos = atomicAdd(&cnt[b], 1);
            spair[pos] = make_float2(vth[q], vex[q]);
        }
        __syncthreads();

        for (int k = t; k < N; k += NT) {
            float2 pk = spair[k];
            if (pk.y == 0.f) continue;  // diagonal marker
            float v = pk.x;
            int b = (int)(v * scale);
            b = b < 0 ? 0 : (b > NBINS - 1 ? NBINS - 1 : b);
            float S = sufsum[b + 1];
            int q1 = start[b + 1];
            for (int q = start[b]; q < q1; q++) {
                float2 pq = spair[q];
                if (pq.x >= v) S += pq.y;
            }
            prod *= S;
            unsigned pb = __float_as_uint(prod);
            eacc += (int)(pb >> 23);
            prod = __uint_as_float((pb & 0x007fffffu) | 0x3f800000u);
            cntk++;
        }
    }

    double logsum = ((double)(eacc - 127 * cntk)) * 0.6931471805599453
                  + (double)__logf(prod);
    __syncthreads();
    red[t] = (double)sumLg - 0.5 * logsum;
    __syncthreads();
    #pragma unroll
    for (int o = NT / 2; o; o >>= 1) {
        if (t < o) red[t] += red[t + o];
        __syncthreads();
    }
    if (t == 0) {
        g_rowsum[i] = red[0];
        __threadfence();
        lastFlag = (atomicAdd(&g_done, 1) == N - 1);
    }
    __syncthreads();

    if (lastFlag) {   // last CTA: deterministic final reduce
        __threadfence();
        double s = 0.0;
        for (int r = t; r < N; r += NT) s += g_rowsum[r];
        red[t] = s;
        __syncthreads();
        #pragma unroll
        for (int o = NT / 2; o; o >>= 1) {
            if (t < o) red[t] += red[t + o];
            __syncthreads();
        }
        if (t == 0)
            out[0] = (float)(-red[0] / ((double)N * (double)(N - 1)));
    }
}

// ---------------------------------------------------------------------------
extern "C" void kernel_launch(void* const* d_in, const int* in_sizes, int n_in,
                              void* d_out, int out_size) {
    const float* theta = (const float*)d_in[0];
    const float* shift = (const float*)d_in[1];
    const float* feats = (const float*)d_in[2];
    float* out = (float*)d_out;

    size_t row_smem = (size_t)N * 8            // spair
                    + (NBINS + 1) * 8          // sufsum + start
                    + (size_t)NBINS * 4;       // cnt
    cudaFuncSetAttribute(row_kernel, cudaFuncAttributeMaxDynamicSharedMemorySize, (int)row_smem);

    x2_kernel<<<N, 128>>>(feats);

    dim3 grid(N / BM, N / BM);
    gram_kernel<<<grid, 256>>>(feats);

    row_kernel<<<N, NT, row_smem>>>(theta, shift, out);
}